// round 14
// baseline (speedup 1.0000x reference)
#include <cuda_runtime.h>
#include <cuda.h>
#include <cuda_fp16.h>
#include <cstdint>

namespace {
constexpr int Tt = 2048, Ee = 1024, HD = 64;
constexpr int BM = 128, BN = 64;
constexpr int NT = 128;
constexpr int NHtot = 64;
constexpr float SC2 = 0.125f * 1.4426950408889634f;
constexpr int PLANE = 8192;
constexpr int OFF_ZB = 4 * PLANE;          // 8KB zero box
constexpr int SMEM_BYTES = OFF_ZB + 8192;  // 40960 -> 4 CTAs/SM
}

__device__ __align__(128) __half gQ[(size_t)NHtot * Tt * HD];
__device__ __align__(128) __half gK[(size_t)NHtot * Tt * HD];
__device__ __align__(128) __half gV[(size_t)NHtot * Tt * HD];

__device__ __forceinline__ uint32_t s2u(const void* p) {
  return (uint32_t)__cvta_generic_to_shared(p);
}
__device__ __forceinline__ void ldmx4(uint32_t* r, uint32_t a) {
  asm volatile("ldmatrix.sync.aligned.m8n8.x4.shared.b16 {%0,%1,%2,%3},[%4];"
               : "=r"(r[0]), "=r"(r[1]), "=r"(r[2]), "=r"(r[3]) : "r"(a));
}
__device__ __forceinline__ void ldmx4t(uint32_t* r, uint32_t a) {
  asm volatile("ldmatrix.sync.aligned.m8n8.x4.trans.shared.b16 {%0,%1,%2,%3},[%4];"
               : "=r"(r[0]), "=r"(r[1]), "=r"(r[2]), "=r"(r[3]) : "r"(a));
}
__device__ __forceinline__ void mmah(float* c, const uint32_t* a, uint32_t b0, uint32_t b1) {
  asm volatile("mma.sync.aligned.m16n8k16.row.col.f32.f16.f16.f32 "
               "{%0,%1,%2,%3},{%4,%5,%6,%7},{%8,%9},{%0,%1,%2,%3};"
               : "+f"(c[0]), "+f"(c[1]), "+f"(c[2]), "+f"(c[3])
               : "r"(a[0]), "r"(a[1]), "r"(a[2]), "r"(a[3]), "r"(b0), "r"(b1));
}
__device__ __forceinline__ uint32_t packh2(float lo, float hi) {
  __half2 h = __floats2half2_rn(lo, hi);
  return *reinterpret_cast<uint32_t*>(&h);
}
__device__ __forceinline__ float ex2(float x) {
  float r; asm("ex2.approx.f32 %0, %1;" : "=f"(r) : "f"(x)); return r;
}
__device__ __forceinline__ float lg2(float x) {
  float r; asm("lg2.approx.f32 %0, %1;" : "=f"(r) : "f"(x)); return r;
}
__device__ __forceinline__ void cpasync16(uint32_t saddr, const void* g) {
  asm volatile("cp.async.cg.shared.global [%0], [%1], 16;" :: "r"(saddr), "l"(g));
}
__device__ __forceinline__ void cp_commit() { asm volatile("cp.async.commit_group;"); }
__device__ __forceinline__ void tma_st(const CUtensorMap* m, int x, int y, uint32_t s) {
  asm volatile("cp.async.bulk.tensor.2d.global.shared::cta.tile.bulk_group "
               "[%0, {%1, %2}], [%3];" :: "l"(m), "r"(x), "r"(y), "r"(s) : "memory");
}
__device__ __forceinline__ void bulk_commit() {
  asm volatile("cp.async.bulk.commit_group;" ::: "memory");
}
__device__ __forceinline__ void bulk_wait0() {
  asm volatile("cp.async.bulk.wait_group 0;" ::: "memory");
}
__device__ __forceinline__ void fence_proxy() {
  asm volatile("fence.proxy.async;" ::: "memory");
}

__device__ __forceinline__ void issue_tile(const __half* p, uint32_t dst, int tid) {
#pragma unroll
  for (int i = 0; i < 4; i++) {
    int q = tid + i * NT;
    int r = q >> 3, c = q & 7;
    uint32_t off = r * 128 + ((c ^ (r & 7)) << 4);
    cpasync16(dst + off, (const char*)p + r * 128 + c * 16);
  }
}

__device__ __forceinline__ void qk_half(float sacc[2][4][4], uint32_t Kst,
                                        const uint32_t qa[2][4][4],
                                        int lane, int hh) {
  const int bTok = ((lane >> 4) << 3) + (lane & 7);
  const int bSel = (lane >> 3) & 1;
  const int x7 = lane & 7;
#pragma unroll
  for (int ch = 0; ch < 4; ch++) {
#pragma unroll
    for (int pp = 0; pp < 2; pp++) {
      const int p = 2 * hh + pp;
      uint32_t b[4];
      ldmx4(b, Kst + (p * 16 + bTok) * 128 + (((2 * ch + bSel) ^ x7) << 4));
      mmah(sacc[0][2 * pp],     qa[0][ch], b[0], b[1]);
      mmah(sacc[0][2 * pp + 1], qa[0][ch], b[2], b[3]);
      mmah(sacc[1][2 * pp],     qa[1][ch], b[0], b[1]);
      mmah(sacc[1][2 * pp + 1], qa[1][ch], b[2], b[3]);
    }
  }
}

// prepass: fp32 [n][t][e] -> per-head fp16 planes [nh][t][d] (float4 wide)
__global__ __launch_bounds__(256) void conv_kernel(
    const float* __restrict__ Q, const float* __restrict__ K,
    const float* __restrict__ V) {
  const float* src;
  __half* dst;
  if (blockIdx.y == 0)      { src = Q; dst = gQ; }
  else if (blockIdx.y == 1) { src = K; dst = gK; }
  else                      { src = V; dst = gV; }
  size_t i = (size_t)blockIdx.x * 256 + threadIdx.x;
  float4 f = ((const float4*)src)[i];
  int e4 = (int)(i & 255);
  size_t tn = i >> 8;
  int e = e4 << 2, h = e >> 6, d = e & 63;
  int t = (int)(tn & 2047), n = (int)(tn >> 11);
  size_t o = ((((size_t)(n * 16 + h)) * Tt + t) * HD + d) >> 1;
  ((uint2*)dst)[o >> 1] = make_uint2(packh2(f.x, f.y), packh2(f.z, f.w));
}

// fused attention: fp16 mma, BM=128, 4 CTAs/SM forced, TMA zero-fill
__global__ __launch_bounds__(NT, 4) void fused_attn_kernel(
    const __grid_constant__ CUtensorMap tmap,
    float* __restrict__ attn, float* __restrict__ Y) {
  extern __shared__ char smem[];
  const uint32_t sb = s2u(smem);
  const uint32_t P[4] = {sb, sb + PLANE, sb + 2 * PLANE, sb + 3 * PLANE};

  const int nh = blockIdx.y, n = nh >> 4;
  const int q0 = ((int)gridDim.x - 1 - (int)blockIdx.x) * BM;  // heavy-first
  const int tid = threadIdx.x, warp = tid >> 5, lane = tid & 31;
  const int ktl = (q0 >> 6) + 1;
  const int rowbase = nh * Tt + q0;

  const size_t hb = (size_t)nh * Tt * HD;
  const __half* Kp = gK + hb;
  const __half* Vp = gV + hb;

  // ---- prologue: zero zbuf; Q -> P2/P3; K0,K1 -> P0,P1 ----
#pragma unroll
  for (int i = 0; i < 4; i++)
    *(float4*)(smem + OFF_ZB + (tid + i * NT) * 16) =
        make_float4(0.f, 0.f, 0.f, 0.f);
  issue_tile(gQ + hb + (size_t)q0 * HD, P[2], tid);
  issue_tile(gQ + hb + (size_t)(q0 + 64) * HD, P[3], tid);
  cp_commit();
  issue_tile(Kp, P[0], tid);
  cp_commit();
  {
    int t1 = ktl >= 1 ? 1 : 0;
    issue_tile(Kp + (size_t)t1 * BN * HD, P[1], tid);
    cp_commit();
  }
  asm volatile("cp.async.wait_group 2;");   // Q landed
  __syncthreads();

  // zero-fill upper triangle via TMA (streams during pass 1)
  if (tid == 0 && q0 + BM < Tt) {
    fence_proxy();
    for (int x = q0 + BM; x < Tt; x += 32) {
      tma_st(&tmap, x, rowbase, sb + OFF_ZB);
      tma_st(&tmap, x, rowbase + 64, sb + OFF_ZB);
    }
    bulk_commit();
  }

  uint32_t qa[2][4][4];
  {
    const int ar = (warp << 4) + (lane & 15);
    const int aSel = lane >> 4;
    const int x7a = ar & 7;
#pragma unroll
    for (int rb = 0; rb < 2; rb++)
#pragma unroll
      for (int ch = 0; ch < 4; ch++)
        ldmx4(qa[rb][ch],
              P[2 + rb] + ar * 128 + (((2 * ch + aSel) ^ x7a) << 4));
  }
  __syncthreads();   // all warps done reading Q before P[2] reuse

  int rowA[2];
  rowA[0] = q0 + (warp << 4) + (lane >> 2);
  rowA[1] = rowA[0] + 64;
  const int cOff = 2 * (lane & 3);

  // ============ pass 1: row sums (proven 3-ring P[0..2], dist-2 prefetch) ====
  float rs[2][2] = {{0.f, 0.f}, {0.f, 0.f}};
  for (int t = 0; t <= ktl; t++) {
    asm volatile("cp.async.wait_group 1;");   // K_t ready (K_{t+1} may fly)
    __syncthreads();
    {
      int tt = t + 2 <= ktl ? t + 2 : ktl;
      issue_tile(Kp + (size_t)tt * BN * HD, P[(t + 2) % 3], tid);
      cp_commit();
    }
    const uint32_t Kst = P[t % 3];
    const int k0 = t * BN;
#pragma unroll
    for (int hh = 0; hh < 2; hh++) {
      float sacc[2][4][4];
#pragma unroll
      for (int rb = 0; rb < 2; rb++)
#pragma unroll
        for (int i = 0; i < 4; i++)
#pragma unroll
          for (int j = 0; j < 4; j++) sacc[rb][i][j] = 0.f;
      qk_half(sacc, Kst, qa, lane, hh);
#pragma unroll
      for (int rb = 0; rb < 2; rb++) {
        const int ra = rowA[rb];
        const bool msk = (k0 + BN - 1) > ra;
#pragma unroll
        for (int pp = 0; pp < 2; pp++)
#pragma unroll
          for (int s = 0; s < 2; s++) {
            const float* f = sacc[rb][2 * pp + s];
            const int c = k0 + (2 * hh + pp) * 16 + 8 * s + cOff;
            float e0 = ex2(f[0] * SC2);
            float e1 = ex2(f[1] * SC2);
            float e2 = ex2(f[2] * SC2);
            float e3 = ex2(f[3] * SC2);
            if (msk) {
              if (c     > ra)     e0 = 0.f;
              if (c + 1 > ra)     e1 = 0.f;
              if (c     > ra + 8) e2 = 0.f;
              if (c + 1 > ra + 8) e3 = 0.f;
            }
            rs[rb][0] += e0 + e1;
            rs[rb][1] += e2 + e3;
          }
      }
    }
  }
  float il[2][2];
#pragma unroll
  for (int rb = 0; rb < 2; rb++)
#pragma unroll
    for (int j = 0; j < 2; j++) {
      float v = rs[rb][j];
      v += __shfl_xor_sync(0xffffffffu, v, 1);
      v += __shfl_xor_sync(0xffffffffu, v, 2);
      il[rb][j] = -lg2(v);
    }

  // ================= pass 2: attn write + P@V =================
  asm volatile("cp.async.wait_group 0;");
  __syncthreads();
  issue_tile(Kp, P[0], tid);
  issue_tile(Vp, P[2], tid);
  cp_commit();
  {
    int t1 = ktl >= 1 ? 1 : 0;
    issue_tile(Kp + (size_t)t1 * BN * HD, P[1], tid);
    issue_tile(Vp + (size_t)t1 * BN * HD, P[3], tid);
    cp_commit();
  }

  float yacc[2][8][4];
#pragma unroll
  for (int rb = 0; rb < 2; rb++)
#pragma unroll
    for (int i = 0; i < 8; i++)
#pragma unroll
      for (int j = 0; j < 4; j++) yacc[rb][i][j] = 0.f;

  const int vTok = (((lane >> 3) & 1) << 3) + (lane & 7);
  const int vSel = lane >> 4;
  const int x7 = lane & 7;
  float* pA[2];
#pragma unroll
  for (int rb = 0; rb < 2; rb++)
    pA[rb] = attn + ((size_t)nh * Tt + rowA[rb]) * Tt;

  for (int t = 0; t <= ktl; t++) {
    asm volatile("cp.async.wait_group 1;");   // pair_t landed
    __syncthreads();
    const uint32_t Kst = P[t & 1];
    const uint32_t Vst = P[2 + (t & 1)];
    const int k0 = t * BN;

#pragma unroll
    for (int hh = 0; hh < 2; hh++) {
      float sacc[2][4][4];
#pragma unroll
      for (int rb = 0; rb < 2; rb++)
#pragma unroll
        for (int i = 0; i < 4; i++)
#pragma unroll
          for (int j = 0; j < 4; j++) sacc[rb][i][j] = 0.f;
      qk_half(sacc, Kst, qa, lane, hh);

#pragma unroll
      for (int pp = 0; pp < 2; pp++) {
        const int p = 2 * hh + pp;
        uint32_t a[2][4];
#pragma unroll
        for (int rb = 0; rb < 2; rb++) {
          const int ra = rowA[rb];
          const bool msk = (k0 + BN - 1) > ra;
          float e[2][4];
#pragma unroll
          for (int s = 0; s < 2; s++) {
            const float* f = sacc[rb][2 * pp + s];
            const int c = k0 + p * 16 + 8 * s + cOff;
            e[s][0] = ex2(fmaf(f[0], SC2, il[rb][0]));
            e[s][1] = ex2(fmaf(f[1], SC2, il[rb][0]));
            e[s][2] = ex2(fmaf(f[2], SC2, il[rb][1]));
            e[s][3] = ex2(fmaf(f[3], SC2, il[rb][1]));
            if (msk) {
              if (c     > ra)     e[s][0] = 0.f;
              if (c + 1 > ra)     e[s][1] = 0.f;
              if (c     > ra + 8) e[s][2] = 0.f;
              if (c + 1 > ra + 8) e[s][3] = 0.f;
            }
            *(float2*)(pA[rb] + c) = make_float2(e[s][0], e[s][1]);
            *(float2*)(pA[rb] + (size_t)8 * Tt + c) = make_float2(e[s][2], e[s][3]);
          }
          a[rb][0] = packh2(e[0][0], e[0][1]);
          a[rb][1] = packh2(e[0][2], e[0][3]);
          a[rb][2] = packh2(e[1][0], e[1][1]);
          a[rb][3] = packh2(e[1][2], e[1][3]);
        }
#pragma unroll
        for (int pd = 0; pd < 4; pd++) {
          uint32_t b[4];
          ldmx4t(b, Vst + (p * 16 + vTok) * 128 + (((2 * pd + vSel) ^ x7) << 4));
          mmah(yacc[0][2 * pd],     a[0], b[0], b[1]);
          mmah(yacc[0][2 * pd + 1], a[0], b[2], b[3]);
          mmah(yacc[1][2 * pd],     a[1], b[0], b[1]);
          mmah(yacc[1][2 * pd + 1], a[1], b[2], b[3]);
        }
      }
    }

    __syncthreads();   // all reads of pair_t done before refill
    {
      int tt = t + 2 <= ktl ? t + 2 : ktl;
      issue_tile(Kp + (size_t)tt * BN * HD, P[t & 1], tid);
      issue_tile(Vp + (size_t)tt * BN * HD, P[2 + (t & 1)], tid);
      cp_commit();
    }
  }

  // ---- y store ----
  const int h = nh & 15;
#pragma unroll
  for (int rb = 0; rb < 2; rb++) {
    float* y0 = Y + (size_t)(n * Tt + rowA[rb]) * Ee + h * HD;
    float* y1 = y0 + (size_t)8 * Ee;
#pragma unroll
    for (int nf = 0; nf < 8; nf++) {
      const int c = (nf << 3) + cOff;
      *(float2*)(y0 + c) = make_float2(yacc[rb][nf][0], yacc[rb][nf][1]);
      *(float2*)(y1 + c) = make_float2(yacc[rb][nf][2], yacc[rb][nf][3]);
    }
  }
  if (tid == 0) bulk_wait0();   // flush zero-fill TMA before exit
}

// ---------------------------------------------------------------------------
extern "C" void kernel_launch(void* const* d_in, const int* in_sizes, int n_in,
                              void* d_out, int out_size) {
  const float* q = (const float*)d_in[0];
  const float* k = (const float*)d_in[1];
  const float* v = (const float*)d_in[2];

  float* y    = (float*)d_out;
  float* attn = (float*)d_out + (size_t)4 * Tt * Ee;

  CUtensorMap tmap;
  {
    void* fn = nullptr;
    cudaDriverEntryPointQueryResult qr;
    cudaGetDriverEntryPoint("cuTensorMapEncodeTiled", &fn, cudaEnableDefault, &qr);
    typedef CUresult (*EncFn)(CUtensorMap*, CUtensorMapDataType, cuuint32_t, void*,
                              const cuuint64_t*, const cuuint64_t*, const cuuint32_t*,
                              const cuuint32_t*, CUtensorMapInterleave,
                              CUtensorMapSwizzle, CUtensorMapL2promotion,
                              CUtensorMapFloatOOBfill);
    cuuint64_t dims[2] = {(cuuint64_t)Tt, (cuuint64_t)NHtot * Tt};
    cuuint64_t strides[1] = {(cuuint64_t)Tt * 4};
    cuuint32_t box[2] = {32, 64};
    cuuint32_t es[2] = {1, 1};
    ((EncFn)fn)(&tmap, CU_TENSOR_MAP_DATA_TYPE_FLOAT32, 2, attn, dims, strides,
                box, es, CU_TENSOR_MAP_INTERLEAVE_NONE, CU_TENSOR_MAP_SWIZZLE_128B,
                CU_TENSOR_MAP_L2_PROMOTION_L2_128B, CU_TENSOR_MAP_FLOAT_OOB_FILL_NONE);
  }

  dim3 cg((unsigned)((size_t)4 * Tt * (Ee / 4) / 256), 3);
  conv_kernel<<<cg, 256>>>(q, k, v);

  cudaFuncSetAttribute(fused_attn_kernel,
                       cudaFuncAttributeMaxDynamicSharedMemorySize, SMEM_BYTES);
  dim3 grid(Tt / BM, NHtot);
  fused_attn_kernel<<<grid, NT, SMEM_BYTES>>>(tmap, attn, y);
}

// round 15
// speedup vs baseline: 1.4019x; 1.4019x over previous
#include <cuda_runtime.h>
#include <cuda.h>
#include <cuda_fp16.h>
#include <cstdint>

namespace {
constexpr int Tt = 2048, Ee = 1024, HD = 64;
constexpr int BM = 128, BN = 64;
constexpr int NT = 128;
constexpr int NHtot = 64;
constexpr float SC2 = 0.125f * 1.4426950408889634f;
constexpr int PLANE = 8192;
constexpr int OFF_ZB = 6 * PLANE;          // 8KB zero box
constexpr int SMEM_BYTES = OFF_ZB + 8192;  // 57344 -> 3 CTAs/SM
}

__device__ __align__(128) __half gQ[(size_t)NHtot * Tt * HD];
__device__ __align__(128) __half gK[(size_t)NHtot * Tt * HD];
__device__ __align__(128) __half gV[(size_t)NHtot * Tt * HD];

__device__ __forceinline__ uint32_t s2u(const void* p) {
  return (uint32_t)__cvta_generic_to_shared(p);
}
__device__ __forceinline__ void ldmx4(uint32_t* r, uint32_t a) {
  asm volatile("ldmatrix.sync.aligned.m8n8.x4.shared.b16 {%0,%1,%2,%3},[%4];"
               : "=r"(r[0]), "=r"(r[1]), "=r"(r[2]), "=r"(r[3]) : "r"(a));
}
__device__ __forceinline__ void ldmx4t(uint32_t* r, uint32_t a) {
  asm volatile("ldmatrix.sync.aligned.m8n8.x4.trans.shared.b16 {%0,%1,%2,%3},[%4];"
               : "=r"(r[0]), "=r"(r[1]), "=r"(r[2]), "=r"(r[3]) : "r"(a));
}
__device__ __forceinline__ void mmah(float* c, const uint32_t* a, uint32_t b0, uint32_t b1) {
  asm volatile("mma.sync.aligned.m16n8k16.row.col.f32.f16.f16.f32 "
               "{%0,%1,%2,%3},{%4,%5,%6,%7},{%8,%9},{%0,%1,%2,%3};"
               : "+f"(c[0]), "+f"(c[1]), "+f"(c[2]), "+f"(c[3])
               : "r"(a[0]), "r"(a[1]), "r"(a[2]), "r"(a[3]), "r"(b0), "r"(b1));
}
__device__ __forceinline__ uint32_t packh2(float lo, float hi) {
  __half2 h = __floats2half2_rn(lo, hi);
  return *reinterpret_cast<uint32_t*>(&h);
}
__device__ __forceinline__ float ex2(float x) {
  float r; asm("ex2.approx.f32 %0, %1;" : "=f"(r) : "f"(x)); return r;
}
__device__ __forceinline__ float lg2(float x) {
  float r; asm("lg2.approx.f32 %0, %1;" : "=f"(r) : "f"(x)); return r;
}
__device__ __forceinline__ void cpasync16(uint32_t saddr, const void* g) {
  asm volatile("cp.async.cg.shared.global [%0], [%1], 16;" :: "r"(saddr), "l"(g));
}
__device__ __forceinline__ void cp_commit() { asm volatile("cp.async.commit_group;"); }
__device__ __forceinline__ void tma_st(const CUtensorMap* m, int x, int y, uint32_t s) {
  asm volatile("cp.async.bulk.tensor.2d.global.shared::cta.tile.bulk_group "
               "[%0, {%1, %2}], [%3];" :: "l"(m), "r"(x), "r"(y), "r"(s) : "memory");
}
__device__ __forceinline__ void bulk_commit() {
  asm volatile("cp.async.bulk.commit_group;" ::: "memory");
}
__device__ __forceinline__ void bulk_wait0() {
  asm volatile("cp.async.bulk.wait_group 0;" ::: "memory");
}
__device__ __forceinline__ void fence_proxy() {
  asm volatile("fence.proxy.async;" ::: "memory");
}
__device__ __forceinline__ void stcs2(float* p, float a, float b) {
  asm volatile("st.global.cs.v2.f32 [%0], {%1, %2};" :: "l"(p), "f"(a), "f"(b)
               : "memory");
}

__device__ __forceinline__ void issue_tile(const __half* p, uint32_t dst, int tid) {
#pragma unroll
  for (int i = 0; i < 4; i++) {
    int q = tid + i * NT;
    int r = q >> 3, c = q & 7;
    uint32_t off = r * 128 + ((c ^ (r & 7)) << 4);
    cpasync16(dst + off, (const char*)p + r * 128 + c * 16);
  }
}

__device__ __forceinline__ void qk_half(float sacc[2][4][4], uint32_t Kst,
                                        const uint32_t qa[2][4][4],
                                        int lane, int hh) {
  const int bTok = ((lane >> 4) << 3) + (lane & 7);
  const int bSel = (lane >> 3) & 1;
  const int x7 = lane & 7;
#pragma unroll
  for (int ch = 0; ch < 4; ch++) {
#pragma unroll
    for (int pp = 0; pp < 2; pp++) {
      const int p = 2 * hh + pp;
      uint32_t b[4];
      ldmx4(b, Kst + (p * 16 + bTok) * 128 + (((2 * ch + bSel) ^ x7) << 4));
      mmah(sacc[0][2 * pp],     qa[0][ch], b[0], b[1]);
      mmah(sacc[0][2 * pp + 1], qa[0][ch], b[2], b[3]);
      mmah(sacc[1][2 * pp],     qa[1][ch], b[0], b[1]);
      mmah(sacc[1][2 * pp + 1], qa[1][ch], b[2], b[3]);
    }
  }
}

// prepass: fp32 [n][t][e] -> per-head fp16 planes [nh][t][d] (float4 wide)
__global__ __launch_bounds__(256) void conv_kernel(
    const float* __restrict__ Q, const float* __restrict__ K,
    const float* __restrict__ V) {
  const float* src;
  __half* dst;
  if (blockIdx.y == 0)      { src = Q; dst = gQ; }
  else if (blockIdx.y == 1) { src = K; dst = gK; }
  else                      { src = V; dst = gV; }
  size_t i = (size_t)blockIdx.x * 256 + threadIdx.x;
  float4 f = ((const float4*)src)[i];
  int e4 = (int)(i & 255);
  size_t tn = i >> 8;
  int e = e4 << 2, h = e >> 6, d = e & 63;
  int t = (int)(tn & 2047), n = (int)(tn >> 11);
  size_t o = ((((size_t)(n * 16 + h)) * Tt + t) * HD + d) >> 1;
  ((uint2*)dst)[o >> 1] = make_uint2(packh2(f.x, f.y), packh2(f.z, f.w));
}

// fused attention: R10 structure + TMA zero-fill + streaming stores
__global__ __launch_bounds__(NT, 3) void fused_attn_kernel(
    const __grid_constant__ CUtensorMap tmap,
    float* __restrict__ attn, float* __restrict__ Y) {
  extern __shared__ char smem[];
  const uint32_t sb = s2u(smem);
  const uint32_t SK[3] = {sb, sb + PLANE, sb + 2 * PLANE};
  const uint32_t SV[3] = {sb + 3 * PLANE, sb + 4 * PLANE, sb + 5 * PLANE};

  const int nh = blockIdx.y, n = nh >> 4;
  const int q0 = ((int)gridDim.x - 1 - (int)blockIdx.x) * BM;  // heavy-first
  const int tid = threadIdx.x, warp = tid >> 5, lane = tid & 31;
  const int ktl = (q0 >> 6) + 1;
  const int rowbase = nh * Tt + q0;

  const size_t hb = (size_t)nh * Tt * HD;
  const __half* Kp = gK + hb;
  const __half* Vp = gV + hb;

  // ---- prologue: zero zbuf; Q -> SV0/SV1; K0,K1 -> SK0,SK1 ----
#pragma unroll
  for (int i = 0; i < 4; i++)
    *(float4*)(smem + OFF_ZB + (tid + i * NT) * 16) =
        make_float4(0.f, 0.f, 0.f, 0.f);
  issue_tile(gQ + hb + (size_t)q0 * HD, SV[0], tid);
  issue_tile(gQ + hb + (size_t)(q0 + 64) * HD, SV[1], tid);
  cp_commit();
  issue_tile(Kp, SK[0], tid);
  cp_commit();
  {
    int t1 = ktl >= 1 ? 1 : 0;
    issue_tile(Kp + (size_t)t1 * BN * HD, SK[1], tid);
    cp_commit();
  }
  asm volatile("cp.async.wait_group 2;");   // Q landed
  __syncthreads();

  // zero-fill upper triangle via TMA (streams during pass 1)
  if (tid == 0 && q0 + BM < Tt) {
    fence_proxy();
    for (int x = q0 + BM; x < Tt; x += 32) {
      tma_st(&tmap, x, rowbase, sb + OFF_ZB);
      tma_st(&tmap, x, rowbase + 64, sb + OFF_ZB);
    }
    bulk_commit();
  }

  uint32_t qa[2][4][4];
  {
    const int ar = (warp << 4) + (lane & 15);
    const int aSel = lane >> 4;
    const int x7a = ar & 7;
#pragma unroll
    for (int rb = 0; rb < 2; rb++)
#pragma unroll
      for (int ch = 0; ch < 4; ch++)
        ldmx4(qa[rb][ch],
              SV[rb] + ar * 128 + (((2 * ch + aSel) ^ x7a) << 4));
  }
  __syncthreads();   // Q reads done before SV reuse

  int rowA[2];
  rowA[0] = q0 + (warp << 4) + (lane >> 2);
  rowA[1] = rowA[0] + 64;
  const int cOff = 2 * (lane & 3);

  // ========== pass 1: row sums (3-stage K ring, dist-2 prefetch) ==========
  float rs[2][2] = {{0.f, 0.f}, {0.f, 0.f}};
  for (int t = 0; t <= ktl; t++) {
    asm volatile("cp.async.wait_group 1;");
    __syncthreads();
    {
      int tt = t + 2 <= ktl ? t + 2 : ktl;
      issue_tile(Kp + (size_t)tt * BN * HD, SK[(t + 2) % 3], tid);
      cp_commit();
    }
    const uint32_t Kst = SK[t % 3];
    const int k0 = t * BN;
#pragma unroll
    for (int hh = 0; hh < 2; hh++) {
      float sacc[2][4][4];
#pragma unroll
      for (int rb = 0; rb < 2; rb++)
#pragma unroll
        for (int i = 0; i < 4; i++)
#pragma unroll
          for (int j = 0; j < 4; j++) sacc[rb][i][j] = 0.f;
      qk_half(sacc, Kst, qa, lane, hh);
#pragma unroll
      for (int rb = 0; rb < 2; rb++) {
        const int ra = rowA[rb];
        const bool msk = (k0 + BN - 1) > ra;
#pragma unroll
        for (int pp = 0; pp < 2; pp++)
#pragma unroll
          for (int s = 0; s < 2; s++) {
            const float* f = sacc[rb][2 * pp + s];
            const int c = k0 + (2 * hh + pp) * 16 + 8 * s + cOff;
            float e0 = ex2(f[0] * SC2);
            float e1 = ex2(f[1] * SC2);
            float e2 = ex2(f[2] * SC2);
            float e3 = ex2(f[3] * SC2);
            if (msk) {
              if (c     > ra)     e0 = 0.f;
              if (c + 1 > ra)     e1 = 0.f;
              if (c     > ra + 8) e2 = 0.f;
              if (c + 1 > ra + 8) e3 = 0.f;
            }
            rs[rb][0] += e0 + e1;
            rs[rb][1] += e2 + e3;
          }
      }
    }
  }
  float il[2][2];
#pragma unroll
  for (int rb = 0; rb < 2; rb++)
#pragma unroll
    for (int j = 0; j < 2; j++) {
      float v = rs[rb][j];
      v += __shfl_xor_sync(0xffffffffu, v, 1);
      v += __shfl_xor_sync(0xffffffffu, v, 2);
      il[rb][j] = -lg2(v);
    }

  // ================= pass 2: attn write + P@V =================
  asm volatile("cp.async.wait_group 0;");
  __syncthreads();
  issue_tile(Kp, SK[0], tid);
  issue_tile(Vp, SV[0], tid);
  cp_commit();
  {
    int t1 = ktl >= 1 ? 1 : 0;
    issue_tile(Kp + (size_t)t1 * BN * HD, SK[1], tid);
    issue_tile(Vp + (size_t)t1 * BN * HD, SV[1], tid);
    cp_commit();
  }

  float yacc[2][8][4];
#pragma unroll
  for (int rb = 0; rb < 2; rb++)
#pragma unroll
    for (int i = 0; i < 8; i++)
#pragma unroll
      for (int j = 0; j < 4; j++) yacc[rb][i][j] = 0.f;

  const int vTok = (((lane >> 3) & 1) << 3) + (lane & 7);
  const int vSel = lane >> 4;
  const int x7 = lane & 7;
  float* pA[2];
#pragma unroll
  for (int rb = 0; rb < 2; rb++)
    pA[rb] = attn + ((size_t)nh * Tt + rowA[rb]) * Tt;

  for (int t = 0; t <= ktl; t++) {
    asm volatile("cp.async.wait_group 1;");   // pair_t landed
    __syncthreads();
    {
      int tt = t + 2 <= ktl ? t + 2 : ktl;
      issue_tile(Kp + (size_t)tt * BN * HD, SK[(t + 2) % 3], tid);
      issue_tile(Vp + (size_t)tt * BN * HD, SV[(t + 2) % 3], tid);
      cp_commit();
    }
    const uint32_t Kst = SK[t % 3];
    const uint32_t Vst = SV[t % 3];
    const int k0 = t * BN;

#pragma unroll
    for (int hh = 0; hh < 2; hh++) {
      float sacc[2][4][4];
#pragma unroll
      for (int rb = 0; rb < 2; rb++)
#pragma unroll
        for (int i = 0; i < 4; i++)
#pragma unroll
          for (int j = 0; j < 4; j++) sacc[rb][i][j] = 0.f;
      qk_half(sacc, Kst, qa, lane, hh);

#pragma unroll
      for (int pp = 0; pp < 2; pp++) {
        const int p = 2 * hh + pp;
        uint32_t a[2][4];
#pragma unroll
        for (int rb = 0; rb < 2; rb++) {
          const int ra = rowA[rb];
          const bool msk = (k0 + BN - 1) > ra;
          float e[2][4];
#pragma unroll
          for (int s = 0; s < 2; s++) {
            const float* f = sacc[rb][2 * pp + s];
            const int c = k0 + p * 16 + 8 * s + cOff;
            e[s][0] = ex2(fmaf(f[0], SC2, il[rb][0]));
            e[s][1] = ex2(fmaf(f[1], SC2, il[rb][0]));
            e[s][2] = ex2(fmaf(f[2], SC2, il[rb][1]));
            e[s][3] = ex2(fmaf(f[3], SC2, il[rb][1]));
            if (msk) {
              if (c     > ra)     e[s][0] = 0.f;
              if (c + 1 > ra)     e[s][1] = 0.f;
              if (c     > ra + 8) e[s][2] = 0.f;
              if (c + 1 > ra + 8) e[s][3] = 0.f;
            }
            stcs2(pA[rb] + c, e[s][0], e[s][1]);
            stcs2(pA[rb] + (size_t)8 * Tt + c, e[s][2], e[s][3]);
          }
          a[rb][0] = packh2(e[0][0], e[0][1]);
          a[rb][1] = packh2(e[0][2], e[0][3]);
          a[rb][2] = packh2(e[1][0], e[1][1]);
          a[rb][3] = packh2(e[1][2], e[1][3]);
        }
#pragma unroll
        for (int pd = 0; pd < 4; pd++) {
          uint32_t b[4];
          ldmx4t(b, Vst + (p * 16 + vTok) * 128 + (((2 * pd + vSel) ^ x7) << 4));
          mmah(yacc[0][2 * pd],     a[0], b[0], b[1]);
          mmah(yacc[0][2 * pd + 1], a[0], b[2], b[3]);
          mmah(yacc[1][2 * pd],     a[1], b[0], b[1]);
          mmah(yacc[1][2 * pd + 1], a[1], b[2], b[3]);
        }
      }
    }
  }

  // ---- y store (streaming) ----
  const int h = nh & 15;
#pragma unroll
  for (int rb = 0; rb < 2; rb++) {
    float* y0 = Y + (size_t)(n * Tt + rowA[rb]) * Ee + h * HD;
    float* y1 = y0 + (size_t)8 * Ee;
#pragma unroll
    for (int nf = 0; nf < 8; nf++) {
      const int c = (nf << 3) + cOff;
      stcs2(y0 + c, yacc[rb][nf][0], yacc[rb][nf][1]);
      stcs2(y1 + c, yacc[rb][nf][2], yacc[rb][nf][3]);
    }
  }
  if (tid == 0) bulk_wait0();   // flush zero-fill TMA before exit
}

// ---------------------------------------------------------------------------
extern "C" void kernel_launch(void* const* d_in, const int* in_sizes, int n_in,
                              void* d_out, int out_size) {
  const float* q = (const float*)d_in[0];
  const float* k = (const float*)d_in[1];
  const float* v = (const float*)d_in[2];

  float* y    = (float*)d_out;
  float* attn = (float*)d_out + (size_t)4 * Tt * Ee;

  CUtensorMap tmap;
  {
    void* fn = nullptr;
    cudaDriverEntryPointQueryResult qr;
    cudaGetDriverEntryPoint("cuTensorMapEncodeTiled", &fn, cudaEnableDefault, &qr);
    typedef CUresult (*EncFn)(CUtensorMap*, CUtensorMapDataType, cuuint32_t, void*,
                              const cuuint64_t*, const cuuint64_t*, const cuuint32_t*,
                              const cuuint32_t*, CUtensorMapInterleave,
                              CUtensorMapSwizzle, CUtensorMapL2promotion,
                              CUtensorMapFloatOOBfill);
    cuuint64_t dims[2] = {(cuuint64_t)Tt, (cuuint64_t)NHtot * Tt};
    cuuint64_t strides[1] = {(cuuint64_t)Tt * 4};
    cuuint32_t box[2] = {32, 64};
    cuuint32_t es[2] = {1, 1};
    ((EncFn)fn)(&tmap, CU_TENSOR_MAP_DATA_TYPE_FLOAT32, 2, attn, dims, strides,
                box, es, CU_TENSOR_MAP_INTERLEAVE_NONE, CU_TENSOR_MAP_SWIZZLE_128B,
                CU_TENSOR_MAP_L2_PROMOTION_L2_128B, CU_TENSOR_MAP_FLOAT_OOB_FILL_NONE);
  }

  dim3 cg((unsigned)((size_t)4 * Tt * (Ee / 4) / 256), 3);
  conv_kernel<<<cg, 256>>>(q, k, v);

  cudaFuncSetAttribute(fused_attn_kernel,
                       cudaFuncAttributeMaxDynamicSharedMemorySize, SMEM_BYTES);
  dim3 grid(Tt / BM, NHtot);
  fused_attn_kernel<<<grid, NT, SMEM_BYTES>>>(tmap, attn, y);
}

// round 16
// speedup vs baseline: 1.4196x; 1.0126x over previous
#include <cuda_runtime.h>
#include <cuda_fp16.h>
#include <cstdint>

namespace {
constexpr int Tt = 2048, Ee = 1024, HD = 64;
constexpr int BM = 128, BN = 64;
constexpr int NT = 128;             // 4 warps, 2 row-blocks each
constexpr int NHtot = 64;
constexpr float SC2 = 0.125f * 1.4426950408889634f;   // scale * log2(e)
constexpr int PLANE = 8192;         // 64 tokens x 128B
constexpr int SMEM_BYTES = 6 * PLANE;   // 49152
}

// preconverted per-head fp16 planes [nh][t][d]
__device__ __align__(128) __half gQ[(size_t)NHtot * Tt * HD];
__device__ __align__(128) __half gK[(size_t)NHtot * Tt * HD];
__device__ __align__(128) __half gV[(size_t)NHtot * Tt * HD];

__device__ __forceinline__ uint32_t s2u(const void* p) {
  return (uint32_t)__cvta_generic_to_shared(p);
}
__device__ __forceinline__ void ldmx4(uint32_t* r, uint32_t a) {
  asm volatile("ldmatrix.sync.aligned.m8n8.x4.shared.b16 {%0,%1,%2,%3},[%4];"
               : "=r"(r[0]), "=r"(r[1]), "=r"(r[2]), "=r"(r[3]) : "r"(a));
}
__device__ __forceinline__ void ldmx4t(uint32_t* r, uint32_t a) {
  asm volatile("ldmatrix.sync.aligned.m8n8.x4.trans.shared.b16 {%0,%1,%2,%3},[%4];"
               : "=r"(r[0]), "=r"(r[1]), "=r"(r[2]), "=r"(r[3]) : "r"(a));
}
__device__ __forceinline__ void mmah(float* c, const uint32_t* a, uint32_t b0, uint32_t b1) {
  asm volatile("mma.sync.aligned.m16n8k16.row.col.f32.f16.f16.f32 "
               "{%0,%1,%2,%3},{%4,%5,%6,%7},{%8,%9},{%0,%1,%2,%3};"
               : "+f"(c[0]), "+f"(c[1]), "+f"(c[2]), "+f"(c[3])
               : "r"(a[0]), "r"(a[1]), "r"(a[2]), "r"(a[3]), "r"(b0), "r"(b1));
}
__device__ __forceinline__ uint32_t packh2(float lo, float hi) {
  __half2 h = __floats2half2_rn(lo, hi);
  return *reinterpret_cast<uint32_t*>(&h);
}
__device__ __forceinline__ float ex2(float x) {
  float r; asm("ex2.approx.f32 %0, %1;" : "=f"(r) : "f"(x)); return r;
}
__device__ __forceinline__ float lg2(float x) {
  float r; asm("lg2.approx.f32 %0, %1;" : "=f"(r) : "f"(x)); return r;
}
__device__ __forceinline__ void cpasync16(uint32_t saddr, const void* g) {
  asm volatile("cp.async.cg.shared.global [%0], [%1], 16;" :: "r"(saddr), "l"(g));
}
__device__ __forceinline__ void cp_commit() { asm volatile("cp.async.commit_group;"); }

// 64-token fp16 tile (8KB) -> swizzled smem stage
__device__ __forceinline__ void issue_tile(const __half* p, uint32_t dst, int tid) {
#pragma unroll
  for (int i = 0; i < 4; i++) {
    int q = tid + i * NT;
    int r = q >> 3, c = q & 7;
    uint32_t off = r * 128 + ((c ^ (r & 7)) << 4);
    cpasync16(dst + off, (const char*)p + r * 128 + c * 16);
  }
}

// QK for one 32-col half: p-values {2hh, 2hh+1}, BOTH row blocks share each B
__device__ __forceinline__ void qk_half(float sacc[2][4][4], uint32_t Kst,
                                        const uint32_t qa[2][4][4],
                                        int lane, int hh) {
  const int bTok = ((lane >> 4) << 3) + (lane & 7);
  const int bSel = (lane >> 3) & 1;
  const int x7 = lane & 7;
#pragma unroll
  for (int ch = 0; ch < 4; ch++) {
#pragma unroll
    for (int pp = 0; pp < 2; pp++) {
      const int p = 2 * hh + pp;
      uint32_t b[4];
      ldmx4(b, Kst + (p * 16 + bTok) * 128 + (((2 * ch + bSel) ^ x7) << 4));
      mmah(sacc[0][2 * pp],     qa[0][ch], b[0], b[1]);
      mmah(sacc[0][2 * pp + 1], qa[0][ch], b[2], b[3]);
      mmah(sacc[1][2 * pp],     qa[1][ch], b[0], b[1]);
      mmah(sacc[1][2 * pp + 1], qa[1][ch], b[2], b[3]);
    }
  }
}

// ---------------------------------------------------------------------------
// prepass: fp32 [n][t][e] -> per-head fp16 planes [nh][t][d] (float4 wide)
// ---------------------------------------------------------------------------
__global__ __launch_bounds__(256) void conv_kernel(
    const float* __restrict__ Q, const float* __restrict__ K,
    const float* __restrict__ V) {
  const float* src;
  __half* dst;
  if (blockIdx.y == 0)      { src = Q; dst = gQ; }
  else if (blockIdx.y == 1) { src = K; dst = gK; }
  else                      { src = V; dst = gV; }
  size_t i = (size_t)blockIdx.x * 256 + threadIdx.x;   // float4 index
  float4 f = ((const float4*)src)[i];
  int e4 = (int)(i & 255);
  size_t tn = i >> 8;
  int e = e4 << 2, h = e >> 6, d = e & 63;
  int t = (int)(tn & 2047), n = (int)(tn >> 11);
  size_t o = ((((size_t)(n * 16 + h)) * Tt + t) * HD + d) >> 1;
  ((uint2*)dst)[o >> 1] = make_uint2(packh2(f.x, f.y), packh2(f.z, f.w));
}

// ---------------------------------------------------------------------------
// fused attention: fp16 mma, BM=128 (2 row-blocks/warp), split-N epilogue
// (identical to the R10 kernel — fastest measured: 296.4 us)
// ---------------------------------------------------------------------------
__global__ __launch_bounds__(NT, 3) void fused_attn_kernel(
    float* __restrict__ attn, float* __restrict__ Y) {
  extern __shared__ char smem[];
  const uint32_t sb = s2u(smem);
  const uint32_t SK[3] = {sb, sb + PLANE, sb + 2 * PLANE};
  const uint32_t SV[3] = {sb + 3 * PLANE, sb + 4 * PLANE, sb + 5 * PLANE};

  const int nh = blockIdx.y, n = nh >> 4;
  const int q0 = ((int)gridDim.x - 1 - (int)blockIdx.x) * BM;  // heavy-first
  const int tid = threadIdx.x, warp = tid >> 5, lane = tid & 31;
  const int ktl = (q0 >> 6) + 1;

  const size_t hb = (size_t)nh * Tt * HD;
  const __half* Kp = gK + hb;
  const __half* Vp = gV + hb;

  // ---- prologue: Q(2 tiles) -> SV[0..1]; K0 -> SK0; K1 -> SK1 ----
  issue_tile(gQ + hb + (size_t)q0 * HD, SV[0], tid);
  issue_tile(gQ + hb + (size_t)(q0 + 64) * HD, SV[1], tid);
  cp_commit();
  issue_tile(Kp, SK[0], tid);
  cp_commit();
  {
    int t1 = ktl >= 1 ? 1 : 0;
    issue_tile(Kp + (size_t)t1 * BN * HD, SK[1], tid);
    cp_commit();
  }
  asm volatile("cp.async.wait_group 2;");
  __syncthreads();
  uint32_t qa[2][4][4];
  {
    const int ar = (warp << 4) + (lane & 15);
    const int aSel = lane >> 4;
    const int x7a = ar & 7;
#pragma unroll
    for (int rb = 0; rb < 2; rb++)
#pragma unroll
      for (int ch = 0; ch < 4; ch++)
        ldmx4(qa[rb][ch],
              SV[0] + (rb * 64 + ar) * 128 + (((2 * ch + aSel) ^ x7a) << 4));
  }

  int rowA[2];
  rowA[0] = q0 + (warp << 4) + (lane >> 2);
  rowA[1] = rowA[0] + 64;
  const int cOff = 2 * (lane & 3);

  // ================= pass 1: row sums =================
  float rs[2][2] = {{0.f, 0.f}, {0.f, 0.f}};
  for (int t = 0; t <= ktl; t++) {
    asm volatile("cp.async.wait_group 1;");
    __syncthreads();
    {
      int tt = t + 2 <= ktl ? t + 2 : ktl;
      issue_tile(Kp + (size_t)tt * BN * HD, SK[(t + 2) % 3], tid);
      cp_commit();
    }
    const uint32_t Kst = SK[t % 3];
    const int k0 = t * BN;
#pragma unroll
    for (int hh = 0; hh < 2; hh++) {
      float sacc[2][4][4];
#pragma unroll
      for (int rb = 0; rb < 2; rb++)
#pragma unroll
        for (int i = 0; i < 4; i++)
#pragma unroll
          for (int j = 0; j < 4; j++) sacc[rb][i][j] = 0.f;
      qk_half(sacc, Kst, qa, lane, hh);
#pragma unroll
      for (int rb = 0; rb < 2; rb++) {
        const int ra = rowA[rb];
        const bool msk = (k0 + BN - 1) > ra;
#pragma unroll
        for (int pp = 0; pp < 2; pp++)
#pragma unroll
          for (int s = 0; s < 2; s++) {
            const float* f = sacc[rb][2 * pp + s];
            const int c = k0 + (2 * hh + pp) * 16 + 8 * s + cOff;
            float e0 = ex2(f[0] * SC2);
            float e1 = ex2(f[1] * SC2);
            float e2 = ex2(f[2] * SC2);
            float e3 = ex2(f[3] * SC2);
            if (msk) {
              if (c     > ra)     e0 = 0.f;
              if (c + 1 > ra)     e1 = 0.f;
              if (c     > ra + 8) e2 = 0.f;
              if (c + 1 > ra + 8) e3 = 0.f;
            }
            rs[rb][0] += e0 + e1;
            rs[rb][1] += e2 + e3;
          }
      }
    }
  }
  float il[2][2];
#pragma unroll
  for (int rb = 0; rb < 2; rb++)
#pragma unroll
    for (int j = 0; j < 2; j++) {
      float v = rs[rb][j];
      v += __shfl_xor_sync(0xffffffffu, v, 1);
      v += __shfl_xor_sync(0xffffffffu, v, 2);
      il[rb][j] = -lg2(v);
    }

  // ================= pass 2: attn write + P@V =================
  asm volatile("cp.async.wait_group 0;");
  __syncthreads();
  issue_tile(Kp, SK[0], tid);
  issue_tile(Vp, SV[0], tid);
  cp_commit();                          // pair 0
  {
    int t1 = ktl >= 1 ? 1 : 0;
    issue_tile(Kp + (size_t)t1 * BN * HD, SK[1], tid);
    issue_tile(Vp + (size_t)t1 * BN * HD, SV[1], tid);
    cp_commit();                        // pair 1
  }

  // zero-fill fully-masked columns [q0+128, Tt)
  if (q0 + BM < Tt) {
    const int zs = q0 + BM;
    const int w4 = (Tt - zs) >> 2;
    const float4 z = make_float4(0.f, 0.f, 0.f, 0.f);
    float* base = attn + ((size_t)nh * Tt + q0) * Tt + zs;
    for (int r = 0; r < BM; r++) {
      float4* row = (float4*)(base + (size_t)r * Tt);
      for (int c = tid; c < w4; c += NT) row[c] = z;
    }
  }

  float yacc[2][8][4];
#pragma unroll
  for (int rb = 0; rb < 2; rb++)
#pragma unroll
    for (int i = 0; i < 8; i++)
#pragma unroll
      for (int j = 0; j < 4; j++) yacc[rb][i][j] = 0.f;

  const int vTok = (((lane >> 3) & 1) << 3) + (lane & 7);
  const int vSel = lane >> 4;
  const int x7 = lane & 7;
  float* pA[2];
#pragma unroll
  for (int rb = 0; rb < 2; rb++)
    pA[rb] = attn + ((size_t)nh * Tt + rowA[rb]) * Tt;

  for (int t = 0; t <= ktl; t++) {
    asm volatile("cp.async.wait_group 1;");   // pair_t landed
    __syncthreads();
    {
      int tt = t + 2 <= ktl ? t + 2 : ktl;
      issue_tile(Kp + (size_t)tt * BN * HD, SK[(t + 2) % 3], tid);
      issue_tile(Vp + (size_t)tt * BN * HD, SV[(t + 2) % 3], tid);
      cp_commit();
    }
    const uint32_t Kst = SK[t % 3];
    const uint32_t Vst = SV[t % 3];
    const int k0 = t * BN;

#pragma unroll
    for (int hh = 0; hh < 2; hh++) {
      float sacc[2][4][4];
#pragma unroll
      for (int rb = 0; rb < 2; rb++)
#pragma unroll
        for (int i = 0; i < 4; i++)
#pragma unroll
          for (int j = 0; j < 4; j++) sacc[rb][i][j] = 0.f;
      qk_half(sacc, Kst, qa, lane, hh);

#pragma unroll
      for (int pp = 0; pp < 2; pp++) {
        const int p = 2 * hh + pp;
        uint32_t a[2][4];
#pragma unroll
        for (int rb = 0; rb < 2; rb++) {
          const int ra = rowA[rb];
          const bool msk = (k0 + BN - 1) > ra;
          float e[2][4];
#pragma unroll
          for (int s = 0; s < 2; s++) {
            const float* f = sacc[rb][2 * pp + s];
            const int c = k0 + p * 16 + 8 * s + cOff;
            e[s][0] = ex2(fmaf(f[0], SC2, il[rb][0]));
            e[s][1] = ex2(fmaf(f[1], SC2, il[rb][0]));
            e[s][2] = ex2(fmaf(f[2], SC2, il[rb][1]));
            e[s][3] = ex2(fmaf(f[3], SC2, il[rb][1]));
            if (msk) {
              if (c     > ra)     e[s][0] = 0.f;
              if (c + 1 > ra)     e[s][1] = 0.f;
              if (c     > ra + 8) e[s][2] = 0.f;
              if (c + 1 > ra + 8) e[s][3] = 0.f;
            }
            *(float2*)(pA[rb] + c) = make_float2(e[s][0], e[s][1]);
            *(float2*)(pA[rb] + (size_t)8 * Tt + c) = make_float2(e[s][2], e[s][3]);
          }
          a[rb][0] = packh2(e[0][0], e[0][1]);
          a[rb][1] = packh2(e[0][2], e[0][3]);
          a[rb][2] = packh2(e[1][0], e[1][1]);
          a[rb][3] = packh2(e[1][2], e[1][3]);
        }
        // PV for k-chunk cc = p: each V fragment feeds both row blocks
#pragma unroll
        for (int pd = 0; pd < 4; pd++) {
          uint32_t b[4];
          ldmx4t(b, Vst + (p * 16 + vTok) * 128 + (((2 * pd + vSel) ^ x7) << 4));
          mmah(yacc[0][2 * pd],     a[0], b[0], b[1]);
          mmah(yacc[0][2 * pd + 1], a[0], b[2], b[3]);
          mmah(yacc[1][2 * pd],     a[1], b[0], b[1]);
          mmah(yacc[1][2 * pd + 1], a[1], b[2], b[3]);
        }
      }
    }
  }

  // ---- y store ----
  const int h = nh & 15;
#pragma unroll
  for (int rb = 0; rb < 2; rb++) {
    float* y0 = Y + (size_t)(n * Tt + rowA[rb]) * Ee + h * HD;
    float* y1 = y0 + (size_t)8 * Ee;
#pragma unroll
    for (int nf = 0; nf < 8; nf++) {
      const int c = (nf << 3) + cOff;
      *(float2*)(y0 + c) = make_float2(yacc[rb][nf][0], yacc[rb][nf][1]);
      *(float2*)(y1 + c) = make_float2(yacc[rb][nf][2], yacc[rb][nf][3]);
    }
  }
}

// ---------------------------------------------------------------------------
extern "C" void kernel_launch(void* const* d_in, const int* in_sizes, int n_in,
                              void* d_out, int out_size) {
  const float* q = (const float*)d_in[0];
  const float* k = (const float*)d_in[1];
  const float* v = (const float*)d_in[2];

  float* y    = (float*)d_out;
  float* attn = (float*)d_out + (size_t)4 * Tt * Ee;

  dim3 cg((unsigned)((size_t)4 * Tt * (Ee / 4) / 256), 3);
  conv_kernel<<<cg, 256>>>(q, k, v);

  cudaFuncSetAttribute(fused_attn_kernel,
                       cudaFuncAttributeMaxDynamicSharedMemorySize, SMEM_BYTES);
  dim3 grid(Tt / BM, NHtot);
  fused_attn_kernel<<<grid, NT, SMEM_BYTES>>>(attn, y);
}